// round 13
// baseline (speedup 1.0000x reference)
#include <cuda_runtime.h>
#include <cub/cub.cuh>
#include <math.h>

#define NB 8
#define CI 256
#define HH 100
#define WW 100
#define KA 9
#define PP 90000          // anchors per image
#define PRE 3000
#define POST 300
#define NW 94             // 32-bit words to cover PRE bits
#define CAND 3136         // preselected candidates per image (PRE + 136 margin)

#define OFF_CLS  0
#define OFF_REG  1440000
#define OFF_ROIS 4320000
#define OFF_INDS 4329600
#define OFF_ANCH 4332000

typedef unsigned long long ull;

// ---- packed f32x2 ops (sm_103a FFMA2/FADD2, PTX-only) ----
#define FMA2(d, a, b, c) asm("fma.rn.f32x2 %0, %1, %2, %3;" : "=l"(d) : "l"(a), "l"(b), "l"(c))
#define ADD2(d, a, b)    asm("add.rn.f32x2 %0, %1, %2;"     : "=l"(d) : "l"(a), "l"(b))
#define PACK2(d, lo, hi) asm("mov.b64 %0, {%1, %2};"        : "=l"(d) : "r"(__float_as_uint(lo)), "r"(__float_as_uint(hi)))
__device__ __forceinline__ void unpack2(ull v, float& lo, float& hi) {
    unsigned l, h;
    asm("mov.b64 {%0, %1}, %2;" : "=r"(l), "=r"(h) : "l"(v));
    lo = __uint_as_float(l); hi = __uint_as_float(h);
}

// ---- tf32 helpers ----
__device__ __forceinline__ unsigned tf32_hi(float v) {
    unsigned h;
    asm("cvt.rna.tf32.f32 %0, %1;" : "=r"(h) : "f"(v));
    return h;
}

#define MMA_TF32(c, a0, a1, a2, a3, b0, b1) \
    asm("mma.sync.aligned.m16n8k8.row.col.f32.tf32.tf32.f32 " \
        "{%0,%1,%2,%3}, {%4,%5,%6,%7}, {%8,%9}, {%0,%1,%2,%3};" \
        : "+f"((c)[0]), "+f"((c)[1]), "+f"((c)[2]), "+f"((c)[3]) \
        : "r"(a0), "r"(a1), "r"(a2), "r"(a3), "r"(b0), "r"(b1))

// ---- scalar compensated MAC (Dekker 2Prod + Fast2Sum with biased accumulator) ----
#define MAC(H, L, a, b) {                         \
    float p  = __fmul_rn((a), (b));               \
    float pe = __fmaf_rn((a), (b), -p);           \
    float t  = __fadd_rn((H), p);                 \
    float z  = __fsub_rn(t, (H));                 \
    float e  = __fsub_rn(p, z);                   \
    (H) = t;                                      \
    (L) = __fadd_rn((L), __fadd_rn(e, pe));       \
}

// ---------------- scratch (static device memory; no runtime allocation) -------------
__device__ float  g_hhi[NB*CI*HH*WW];        // plain-precision conv output (82 MB)
__device__ float  g_w1tf[CI*9*CI];           // w1 transposed to [ic*9+k][oc]
__device__ unsigned g_k32i[NB*PP], g_k32o[NB*PP], g_vi[NB*PP], g_vo[NB*PP];
__device__ int g_segoff[9]  = {0,90000,180000,270000,360000,450000,540000,630000,720000};
__device__ int g_segoff2[9] = {0,CAND,2*CAND,3*CAND,4*CAND,5*CAND,6*CAND,7*CAND,8*CAND};
__device__ unsigned g_cand[NB*CAND];         // candidate anchor ids per image
__device__ int g_pixflag[NB*10000];
__device__ int g_cnt[NB];
__device__ int g_slotofpix[NB*10000];
__device__ int g_pixofslot[NB*CAND];
__device__ float g_hchi[NB*CAND*CI];         // precise h (hi) per candidate pixel slot
__device__ float g_hclo[NB*CAND*CI];         // precise h (lo)
__device__ double g_cboxd[NB*CAND*4];        // exact f64 boxes per candidate
__device__ ull g_ck[NB*CAND], g_cko[NB*CAND];
__device__ unsigned g_cv[NB*CAND], g_cvo[NB*CAND];
__device__ double g_bsort[NB*PRE*4];
__device__ double g_area[NB*PRE];
__device__ float4 g_bsf[NB*PRE];
__device__ float  g_areaf[NB*PRE];
__device__ int   g_valid[NB*PRE];
__device__ unsigned g_mask[NB*PRE*NW];
__device__ unsigned char g_cubtmp[48u<<20];

// ---------------- anchor base (double math, rounded to f32 = np.float32 array) ------
__device__ __forceinline__ void anchor_ab(int k, float& a0, float& a1, float& a2, float& a3) {
    int ri = k / 3, si = k % 3;
    double r = (ri == 0) ? 0.5 : ((ri == 1) ? 1.0 : 2.0);
    double s = (si == 0) ? 8.0 : ((si == 1) ? 16.0 : 32.0);
    double h = 16.0 * s * sqrt(r);
    double w = 16.0 * s * sqrt(1.0 / r);
    a0 = (float)(8.0 - h / 2.0);
    a1 = (float)(8.0 - w / 2.0);
    a2 = (float)(8.0 + h / 2.0);
    a3 = (float)(8.0 + w / 2.0);
}

// ---------------- weight transpose: [oc][ic][k] -> [ic*9+k][oc] ----------------------
__global__ void wtrans(const float* __restrict__ w1) {
    int idx = blockIdx.x * 256 + threadIdx.x;
    if (idx >= CI * 9 * CI) return;
    int oc = idx % CI;
    int t  = idx / CI;
    int kk = t % 9;
    int ic = t / 9;
    g_w1tf[idx] = w1[(oc * CI + ic) * 9 + kk];
}

// -------- tf32 tensor-core conv 3x3 (split hi/lo, 3 cross-products) ------------------
// block: 128 threads (4 warps); tile: 64 pixels x 128 oc; K = 9 kpos x 256 ic.
// B is staged in smem directly in m16n8k8 fragment layout: lane feeds via LDS.64.
__global__ __launch_bounds__(128) void conv3t(const float* __restrict__ x,
                                              const float* __restrict__ b1) {
    __shared__ float Ah[64][17], Al[64][17];    // A tile hi/lo  (k16 chunk)
    __shared__ float2 Bpk[2][2][16][32];        // [ks][hi/lo][nt][lane] fragment pairs
    int n    = blockIdx.z;
    int ocb  = blockIdx.y * 128;
    int pix0 = blockIdx.x * 64;
    int tid  = threadIdx.x;
    int lane = tid & 31, wid = tid >> 5;
    int gr   = lane >> 2, tg = lane & 3;        // groupID, thread-in-group
    int mrow = wid * 16;

    float c[16][4];
    #pragma unroll
    for (int nt = 0; nt < 16; nt++)
        #pragma unroll
        for (int j = 0; j < 4; j++) c[nt][j] = 0.f;

    int am   = tid & 63;
    int apy  = (pix0 + am) / 100, apx = (pix0 + am) - apy * 100;
    bool apix_ok = (pix0 + am) < 10000;

    for (int kpos = 0; kpos < 9; kpos++) {
        int dy = kpos / 3 - 1, dx = kpos % 3 - 1;
        int gy = apy + dy, gx = apx + dx;
        bool aok = apix_ok && (unsigned)gy < 100u && (unsigned)gx < 100u;
        const float* xbase = x + ((size_t)n * CI * HH + (size_t)gy) * WW + gx;
        for (int icc = 0; icc < 16; icc++) {
            int ic0 = icc * 16;
            // gather A: 64 pixels x 16 ic (shifted x), split hi/lo
            #pragma unroll
            for (int i = 0; i < 8; i++) {
                int kc = i * 2 + (tid >> 6);
                float v = aok ? xbase[(size_t)(ic0 + kc) * (HH * WW)] : 0.f;
                float hv = __uint_as_float(tf32_hi(v));
                Ah[am][kc] = hv;
                Al[am][kc] = __fsub_rn(v, hv);
            }
            // gather B: 16 ic x 128 oc, split hi/lo, scattered into fragment layout
            #pragma unroll
            for (int i = 0; i < 4; i++) {
                int t4 = tid + i * 128;
                int kc = t4 >> 5, o4 = (t4 & 31) * 4;
                float4 v = *(const float4*)&g_w1tf[((ic0 + kc) * 9 + kpos) * CI + ocb + o4];
                int ks   = kc >> 3, r = kc & 7;
                int slot = r >> 2, tg2 = r & 3;
                int nt   = o4 >> 3, grb = o4 & 7;
                float vv0 = v.x, vv1 = v.y, vv2 = v.z, vv3 = v.w;
                #pragma unroll
                for (int j = 0; j < 4; j++) {
                    float val = (j == 0) ? vv0 : ((j == 1) ? vv1 : ((j == 2) ? vv2 : vv3));
                    float hv = __uint_as_float(tf32_hi(val));
                    int lane2 = (grb + j) * 4 + tg2;
                    ((float*)&Bpk[ks][0][nt][lane2])[slot] = hv;
                    ((float*)&Bpk[ks][1][nt][lane2])[slot] = __fsub_rn(val, hv);
                }
            }
            __syncthreads();

            #pragma unroll
            for (int ks = 0; ks < 2; ks++) {
                int k0 = ks * 8;
                unsigned ah0 = __float_as_uint(Ah[mrow + gr][k0 + tg]);
                unsigned ah1 = __float_as_uint(Ah[mrow + gr + 8][k0 + tg]);
                unsigned ah2 = __float_as_uint(Ah[mrow + gr][k0 + tg + 4]);
                unsigned ah3 = __float_as_uint(Ah[mrow + gr + 8][k0 + tg + 4]);
                unsigned al0 = __float_as_uint(Al[mrow + gr][k0 + tg]);
                unsigned al1 = __float_as_uint(Al[mrow + gr + 8][k0 + tg]);
                unsigned al2 = __float_as_uint(Al[mrow + gr][k0 + tg + 4]);
                unsigned al3 = __float_as_uint(Al[mrow + gr + 8][k0 + tg + 4]);
                #pragma unroll
                for (int nt = 0; nt < 16; nt++) {
                    float2 bh = Bpk[ks][0][nt][lane];
                    float2 bl = Bpk[ks][1][nt][lane];
                    unsigned bh0 = __float_as_uint(bh.x), bh1 = __float_as_uint(bh.y);
                    unsigned bl0 = __float_as_uint(bl.x), bl1 = __float_as_uint(bl.y);
                    MMA_TF32(c[nt], ah0, ah1, ah2, ah3, bh0, bh1);
                    MMA_TF32(c[nt], ah0, ah1, ah2, ah3, bl0, bl1);
                    MMA_TF32(c[nt], al0, al1, al2, al3, bh0, bh1);
                }
            }
            __syncthreads();
        }
    }

    // epilogue: bias + relu, write h
    int p0 = pix0 + mrow + gr;
    int p1 = p0 + 8;
    #pragma unroll
    for (int nt = 0; nt < 16; nt++) {
        int oc = ocb + nt * 8 + tg * 2;
        float bia = b1[oc], bib = b1[oc + 1];
        if (p0 < 10000) {
            g_hhi[(size_t)(n * CI + oc) * 10000 + p0]       = fmaxf(c[nt][0] + bia, 0.f);
            g_hhi[(size_t)(n * CI + oc + 1) * 10000 + p0]   = fmaxf(c[nt][1] + bib, 0.f);
        }
        if (p1 < 10000) {
            g_hhi[(size_t)(n * CI + oc) * 10000 + p1]       = fmaxf(c[nt][2] + bia, 0.f);
            g_hhi[(size_t)(n * CI + oc + 1) * 10000 + p1]   = fmaxf(c[nt][3] + bib, 0.f);
        }
    }
}

// ------- plain-fp32 fused heads: cls/reg outputs + approx score sort keys ------------
__global__ __launch_bounds__(128) void heads_fast(const float* __restrict__ wc,
                                                  const float* __restrict__ bc,
                                                  const float* __restrict__ wr,
                                                  const float* __restrict__ br,
                                                  float* __restrict__ out) {
    __shared__ float sw1[64][54];
    int n = blockIdx.y;
    int p = blockIdx.x * 128 + threadIdx.x;

    ull H[27];
    #pragma unroll
    for (int o = 0; o < 27; o++) H[o] = 0ull;

    for (int icb = 0; icb < CI; icb += 64) {
        for (int idx = threadIdx.x; idx < 64 * 54; idx += 128) {
            int ic = idx / 54, oc = idx % 54;
            sw1[ic][oc] = (oc < 18) ? wc[oc * CI + icb + ic]
                                    : wr[(oc - 18) * CI + icb + ic];
        }
        __syncthreads();
        if (p < HH * WW) {
            #pragma unroll 1
            for (int ic = 0; ic < 64; ic++) {
                float hh = g_hhi[(size_t)(n * CI + icb + ic) * (HH * WW) + p];
                ull hhp; PACK2(hhp, hh, hh);
                #pragma unroll
                for (int q = 0; q < 27; q++) {
                    ull wp = *(const ull*)&sw1[ic][q * 2];
                    FMA2(H[q], hhp, wp, H[q]);
                }
            }
        }
        __syncthreads();
    }
    if (p >= HH * WW) return;

    float hs[54];
    #pragma unroll
    for (int q = 0; q < 27; q++) unpack2(H[q], hs[q * 2], hs[q * 2 + 1]);

    float l[18];
    #pragma unroll
    for (int c18 = 0; c18 < 18; c18++) {
        l[c18] = hs[c18] + bc[c18];
        int k = c18 >> 1, cc = c18 & 1;
        out[OFF_CLS + (n * 2 + cc) * PP + p * KA + k] = l[c18];
    }
    #pragma unroll
    for (int k = 0; k < KA; k++) {
        float s = 1.f / (1.f + __expf(l[2 * k] - l[2 * k + 1]));
        int idx = n * PP + p * KA + k;
        g_k32i[idx] = __float_as_uint(s);
        g_vi[idx] = (unsigned)(p * KA + k);
    }
    #pragma unroll
    for (int c36 = 0; c36 < 36; c36++) {
        int k = c36 >> 2, j = c36 & 3;
        out[OFF_REG + n * (PP * 4) + (p * KA + k) * 4 + j] = hs[18 + c36] + br[c36];
    }
}

// ---------------- clear per-run state (graph replays reuse buffers) ------------------
__global__ void clearw() {
    int idx = blockIdx.x * 256 + threadIdx.x;
    if (idx < NB * 10000) g_pixflag[idx] = 0;
    if (idx < NB) g_cnt[idx] = 0;
}

// ---------------- mark candidate anchors + their pixels ------------------------------
__global__ void mark() {
    int idx = blockIdx.x * 256 + threadIdx.x;
    if (idx >= NB * CAND) return;
    int n = idx / CAND, r = idx - n * CAND;
    unsigned i = g_vo[n * PP + r];
    g_cand[idx] = i;
    g_pixflag[n * 10000 + i / KA] = 1;
}

// ---------------- compact flagged pixels into slots ----------------------------------
__global__ void compact() {
    int idx = blockIdx.x * 256 + threadIdx.x;
    if (idx >= NB * 10000) return;
    if (g_pixflag[idx]) {
        int n = idx / 10000, pix = idx - n * 10000;
        int s = atomicAdd(&g_cnt[n], 1);
        g_slotofpix[idx] = s;
        g_pixofslot[n * CAND + s] = pix;
    }
}

// ------ precise conv recompute for flagged pixels (compensated FFMA2) ---------------
// block: 128 threads (2 oc each), 4 pixel-slots per block (R8 proven config)
__global__ __launch_bounds__(128) void precise_h(const float* __restrict__ x,
                                                 const float* __restrict__ b1) {
    __shared__ float sxp[4][2304];
    int n = blockIdx.y;
    int s0 = blockIdx.x * 4;
    int cnt = g_cnt[n];
    if (s0 >= cnt) return;
    int tid = threadIdx.x;

    #pragma unroll
    for (int q = 0; q < 4; q++) {
        int sl = s0 + q;
        int pix = g_pixofslot[n * CAND + ((sl < cnt) ? sl : s0)];
        int py = pix / WW, px = pix - py * WW;
        for (int t = tid; t < 2304; t += 128) {
            int ic = t / 9, k = t - ic * 9;
            int ky = k / 3, kx = k - ky * 3;
            int gy = py + ky - 1, gx = px + kx - 1;
            float v = 0.f;
            if ((unsigned)gy < 100u && (unsigned)gx < 100u)
                v = x[((n * CI + ic) * HH + gy) * WW + gx];
            sxp[q][t] = v;
        }
    }
    __syncthreads();

    const float BIAS = 96.0f;
    ull BIASP, NEG1;
    PACK2(BIASP, BIAS, BIAS);
    PACK2(NEG1, -1.0f, -1.0f);
    ull H[4], L[4];
    #pragma unroll
    for (int q = 0; q < 4; q++) { H[q] = BIASP; L[q] = 0ull; }

    const float* wbase = g_w1tf + tid * 2;
    #pragma unroll 4
    for (int t = 0; t < 2304; t++) {
        ull wp = *(const ull*)(wbase + (size_t)t * CI);
        #pragma unroll
        for (int q = 0; q < 4; q++) {
            float xv = sxp[q][t];
            ull xx; PACK2(xx, xv, xv);
            ull Hn, nd, rr;
            FMA2(Hn, xx, wp, H[q]);
            FMA2(nd, Hn, NEG1, H[q]);
            FMA2(rr, xx, wp, nd);
            ADD2(L[q], L[q], rr);
            H[q] = Hn;
        }
    }

    int oc = tid * 2;
    #pragma unroll
    for (int q = 0; q < 4; q++) {
        if (s0 + q < cnt) {
            float h0, h1, l0, l1;
            unpack2(H[q], h0, h1);
            unpack2(L[q], l0, l1);
            size_t base = (size_t)(n * CAND + s0 + q) * CI;
            double v0 = fmax((double)__fsub_rn(h0, BIAS) + (double)l0 + (double)b1[oc], 0.0);
            float vh0 = (float)v0;
            g_hchi[base + oc] = vh0;
            g_hclo[base + oc] = (float)(v0 - (double)vh0);
            double v1 = fmax((double)__fsub_rn(h1, BIAS) + (double)l1 + (double)b1[oc + 1], 0.0);
            float vh1 = (float)v1;
            g_hchi[base + oc + 1] = vh1;
            g_hclo[base + oc + 1] = (float)(v1 - (double)vh1);
        }
    }
}

// ------ exact logits/score/reg + f64 decode for candidates ---------------------------
__global__ void precise_sr(const float* __restrict__ wc,
                           const float* __restrict__ bc,
                           const float* __restrict__ wr,
                           const float* __restrict__ br,
                           const int* __restrict__ pimw,
                           const int* __restrict__ pimh) {
    int idx = blockIdx.x * 256 + threadIdx.x;
    if (idx >= NB * CAND) return;
    int n = idx / CAND, r = idx - n * CAND;
    unsigned i = g_cand[idx];
    int pix = i / KA, k = i - pix * KA;
    int slot = g_slotofpix[n * 10000 + pix];
    size_t base = (size_t)(n * CAND + slot) * CI;

    const float BIAS = 16.0f;
    float Hh[6], Ll[6];
    #pragma unroll
    for (int ch = 0; ch < 6; ch++) { Hh[ch] = BIAS; Ll[ch] = 0.f; }

    for (int ic = 0; ic < CI; ic++) {
        float hh = g_hchi[base + ic];
        float hl = g_hclo[base + ic];
        #pragma unroll
        for (int ch = 0; ch < 6; ch++) {
            float w = (ch < 2) ? wc[(2 * k + ch) * CI + ic]
                               : wr[(4 * k + ch - 2) * CI + ic];
            MAC(Hh[ch], Ll[ch], hh, w);
            Ll[ch] = __fadd_rn(Ll[ch], __fmul_rn(hl, w));
        }
    }

    double l0 = (double)__fsub_rn(Hh[0], BIAS) + (double)Ll[0] + (double)bc[2 * k];
    double l1 = (double)__fsub_rn(Hh[1], BIAS) + (double)Ll[1] + (double)bc[2 * k + 1];
    double score = 1.0 / (1.0 + exp(l0 - l1));
    double dv[4];
    #pragma unroll
    for (int j = 0; j < 4; j++)
        dv[j] = (double)__fsub_rn(Hh[2 + j], BIAS) + (double)Ll[2 + j]
              + (double)br[4 * k + j];

    // f64 decode (anchors replicate numpy f32 arithmetic, then promote)
    int y = pix / WW, x = pix - y * WW;
    float a0, a1, a2, a3;
    anchor_ab(k, a0, a1, a2, a3);
    float sy = (float)(y * 16), sx0 = (float)(x * 16);
    float af0 = sy + a0, af1 = sx0 + a1, af2 = sy + a2, af3 = sx0 + a3;
    float ahf = af2 - af0, awf = af3 - af1;
    float ayf = af0 + 0.5f * ahf, axf = af1 + 0.5f * awf;
    double ah = (double)ahf, aw = (double)awf, ay = (double)ayf, ax = (double)axf;

    double cy = dv[0] * ah + ay, cx = dv[1] * aw + ax;
    double hb = exp(dv[2]) * ah, wb = exp(dv[3]) * aw;

    int wv = pimw[0], hv = pimh[0];
    double imw = (wv > 65536 || wv < 0) ? (double)__int_as_float(wv) : (double)wv;
    double imh = (hv > 65536 || hv < 0) ? (double)__int_as_float(hv) : (double)hv;

    double y1 = fmin(fmax(cy - 0.5 * hb, 0.0), imh);
    double y2 = fmin(fmax(cy + 0.5 * hb, 0.0), imh);
    double x1 = fmin(fmax(cx - 0.5 * wb, 0.0), imw);
    double x2 = fmin(fmax(cx + 0.5 * wb, 0.0), imw);
    bool big = (y2 - y1 >= 16.0) && (x2 - x1 >= 16.0);

    double* bp = &g_cboxd[(size_t)idx * 4];
    bp[0] = y1; bp[1] = x1; bp[2] = y2; bp[3] = x2;
    g_ck[idx] = big ? __double_as_longlong(score) : 0ull;
    g_cv[idx] = (unsigned)r;
}

// ---------------- gather top PRE per batch (from exact candidate sort) ---------------
__global__ void gather_top2() {
    int idx = blockIdx.x * 256 + threadIdx.x;
    if (idx >= NB * PRE) return;
    int n = idx / PRE, rr = idx - n * PRE;
    ull key = g_cko[n * CAND + rr];
    unsigned cs = g_cvo[n * CAND + rr];
    const double* bp = &g_cboxd[((size_t)n * CAND + cs) * 4];
    double y1 = bp[0], x1 = bp[1], y2 = bp[2], x2 = bp[3];
    double* d = &g_bsort[(size_t)idx * 4];
    d[0] = y1; d[1] = x1; d[2] = y2; d[3] = x2;
    double a = (y2 - y1) * (x2 - x1);
    g_area[idx]  = a;
    g_bsf[idx]   = make_float4((float)y1, (float)x1, (float)y2, (float)x2);
    g_areaf[idx] = (float)a;
    g_valid[idx] = (key != 0ull) ? 1 : 0;
}

// ------- NMS mask: f32 IoU with f64 fallback in a guard band around the threshold ----
__global__ __launch_bounds__(96) void nms_mask() {
    int i = blockIdx.x, n = blockIdx.y;
    float4 bi = g_bsf[n * PRE + i];
    float ai = g_areaf[n * PRE + i];
    int lane = threadIdx.x & 31, wp = threadIdx.x >> 5;
    int wstart = i >> 5;
    for (int w = wstart + wp; w < NW; w += 3) {
        int j = w * 32 + lane;
        bool bit = false;
        if (j < PRE && j > i) {
            float4 bj = g_bsf[n * PRE + j];
            float yy1 = fmaxf(bi.x, bj.x);
            float xx1 = fmaxf(bi.y, bj.y);
            float yy2 = fminf(bi.z, bj.z);
            float xx2 = fminf(bi.w, bj.w);
            float inter = fmaxf(yy2 - yy1, 0.f) * fmaxf(xx2 - xx1, 0.f);
            float iou = inter / (ai + g_areaf[n * PRE + j] - inter + 1e-9f);
            if (fabsf(iou - 0.7f) < 1e-4f) {
                const double* di = &g_bsort[((size_t)n * PRE + i) * 4];
                const double* dj = &g_bsort[((size_t)n * PRE + j) * 4];
                double dy1 = fmax(di[0], dj[0]);
                double dx1 = fmax(di[1], dj[1]);
                double dy2 = fmin(di[2], dj[2]);
                double dx2 = fmin(di[3], dj[3]);
                double dint = fmax(dy2 - dy1, 0.0) * fmax(dx2 - dx1, 0.0);
                double diou = dint / (g_area[n * PRE + i] + g_area[n * PRE + j]
                                      - dint + 1e-9);
                bit = diou > 0.7;
            } else {
                bit = iou > 0.7f;
            }
        }
        unsigned m = __ballot_sync(0xffffffffu, bit);
        if (lane == 0) g_mask[((size_t)n * PRE + i) * NW + w] = m;
    }
}

// ------ serial greedy scan, 1 warp per batch; validity prefolded into registers ------
__global__ __launch_bounds__(32) void nms_scan(float* __restrict__ out) {
    int n = blockIdx.x;
    int lane = threadIdx.x;
    unsigned rm0 = 0, rm1 = 0, rm2 = 0;   // lane holds words lane, lane+32, lane+64

    for (int w = 0; w < NW; w++) {
        int j = w * 32 + lane;
        int v = (j < PRE) ? g_valid[n * PRE + j] : 0;
        unsigned word = __ballot_sync(0xffffffffu, v != 0);
        unsigned inv = ~word;
        int slot = w >> 5, src = w & 31;
        if (lane == src) {
            if (slot == 0) rm0 |= inv;
            else if (slot == 1) rm1 |= inv;
            else rm2 |= inv;
        }
    }

    int count = 0;
    for (int i = 0; i < PRE && count < POST; i++) {
        int wi = i >> 5;
        int slot = wi >> 5;
        int src  = wi & 31;
        unsigned myw = (slot == 0) ? rm0 : ((slot == 1) ? rm1 : rm2);
        unsigned word = __shfl_sync(0xffffffffu, myw, src);
        if (!((word >> (i & 31)) & 1u)) {
            if (lane < 4)
                out[OFF_ROIS + (n * POST + count) * 4 + lane] =
                    (float)g_bsort[((size_t)n * PRE + i) * 4 + lane];
            count++;
            const unsigned* mrow = &g_mask[((size_t)n * PRE + i) * NW];
            int w0 = lane;
            int w1 = lane + 32;
            int w2 = lane + 64;
            if (w0 >= wi && w0 < NW) rm0 |= mrow[w0];
            if (w1 >= wi && w1 < NW) rm1 |= mrow[w1];
            if (w2 >= wi && w2 < NW) rm2 |= mrow[w2];
        }
    }
    for (int m = count; m < POST; m++)
        if (lane < 4) out[OFF_ROIS + (n * POST + m) * 4 + lane] = 0.f;
    for (int m = lane; m < POST; m += 32)
        out[OFF_INDS + n * POST + m] = (float)n;
}

// ---------------- anchors output (f32, replicating numpy f32 arithmetic) -------------
__global__ void anchors_k(float* __restrict__ out) {
    int i = blockIdx.x * 256 + threadIdx.x;
    if (i >= PP) return;
    int cell = i / KA, k = i - cell * KA;
    int y = cell / WW, x = cell - y * WW;
    float a0, a1, a2, a3;
    anchor_ab(k, a0, a1, a2, a3);
    float sy = (float)(y * 16), sx = (float)(x * 16);
    out[OFF_ANCH + i * 4 + 0] = sy + a0;
    out[OFF_ANCH + i * 4 + 1] = sx + a1;
    out[OFF_ANCH + i * 4 + 2] = sy + a2;
    out[OFF_ANCH + i * 4 + 3] = sx + a3;
}

// ---------------- launch -------------------------------------------------------------
extern "C" void kernel_launch(void* const* d_in, const int* in_sizes, int n_in,
                              void* d_out, int out_size) {
    const float* x  = (const float*)d_in[0];
    const float* w1 = (const float*)d_in[1];
    const float* b1 = (const float*)d_in[2];
    const float* wc = (const float*)d_in[3];
    const float* bc = (const float*)d_in[4];
    const float* wr = (const float*)d_in[5];
    const float* br = (const float*)d_in[6];
    const int* imw  = (const int*)d_in[7];
    const int* imh  = (const int*)d_in[8];
    float* out = (float*)d_out;

    wtrans<<<(CI * 9 * CI + 255) / 256, 256>>>(w1);
    conv3t<<<dim3(157, 2, NB), 128>>>(x, b1);
    heads_fast<<<dim3(79, NB), 128>>>(wc, bc, wr, br, out);
    clearw<<<(NB * 10000 + 255) / 256, 256>>>();

    void *pt, *poff, *poff2;
    void *pk32i, *pk32o, *pvi, *pvo, *pck, *pcko, *pcv, *pcvo;
    cudaGetSymbolAddress(&pt, g_cubtmp);
    cudaGetSymbolAddress(&poff, g_segoff);
    cudaGetSymbolAddress(&poff2, g_segoff2);
    cudaGetSymbolAddress(&pk32i, g_k32i);
    cudaGetSymbolAddress(&pk32o, g_k32o);
    cudaGetSymbolAddress(&pvi, g_vi);
    cudaGetSymbolAddress(&pvo, g_vo);
    cudaGetSymbolAddress(&pck, g_ck);
    cudaGetSymbolAddress(&pcko, g_cko);
    cudaGetSymbolAddress(&pcv, g_cv);
    cudaGetSymbolAddress(&pcvo, g_cvo);

    // approx preselect sort: low 8 key bits truncated (order within 1.5e-5 score
    // quantum is arbitrary — safe: mark() consumes the top-CAND as a SET and the
    // exact 64-bit sort later restores true ordering)
    size_t tb = sizeof(g_cubtmp);
    cub::DeviceSegmentedRadixSort::SortPairsDescending(
        pt, tb,
        (const unsigned*)pk32i, (unsigned*)pk32o,
        (const unsigned*)pvi, (unsigned*)pvo,
        NB * PP, NB,
        (const int*)poff, (const int*)poff + 1,
        8, 32, (cudaStream_t)0);

    mark<<<(NB * CAND + 255) / 256, 256>>>();
    compact<<<(NB * 10000 + 255) / 256, 256>>>();
    precise_h<<<dim3(CAND / 4, NB), 128>>>(x, b1);
    precise_sr<<<(NB * CAND + 255) / 256, 256>>>(wc, bc, wr, br, imw, imh);

    size_t tb2 = sizeof(g_cubtmp);
    cub::DeviceSegmentedRadixSort::SortPairsDescending(
        pt, tb2,
        (const ull*)pck, (ull*)pcko,
        (const unsigned*)pcv, (unsigned*)pcvo,
        NB * CAND, NB,
        (const int*)poff2, (const int*)poff2 + 1,
        0, 64, (cudaStream_t)0);

    gather_top2<<<(NB * PRE + 255) / 256, 256>>>();
    nms_mask<<<dim3(PRE, NB), 96>>>();
    nms_scan<<<NB, 32>>>(out);
    anchors_k<<<(PP + 255) / 256, 256>>>(out);
}

// round 14
// speedup vs baseline: 1.4111x; 1.4111x over previous
#include <cuda_runtime.h>
#include <cub/cub.cuh>
#include <math.h>

#define NB 8
#define CI 256
#define HH 100
#define WW 100
#define KA 9
#define PP 90000          // anchors per image
#define PRE 3000
#define POST 300
#define NW 94             // 32-bit words to cover PRE bits
#define CAND 3136         // preselected candidates per image (PRE + 136 margin)

#define OFF_CLS  0
#define OFF_REG  1440000
#define OFF_ROIS 4320000
#define OFF_INDS 4329600
#define OFF_ANCH 4332000

typedef unsigned long long ull;

// ---- packed f32x2 ops (sm_103a FFMA2/FADD2, PTX-only) ----
#define FMA2(d, a, b, c) asm("fma.rn.f32x2 %0, %1, %2, %3;" : "=l"(d) : "l"(a), "l"(b), "l"(c))
#define ADD2(d, a, b)    asm("add.rn.f32x2 %0, %1, %2;"     : "=l"(d) : "l"(a), "l"(b))
#define PACK2(d, lo, hi) asm("mov.b64 %0, {%1, %2};"        : "=l"(d) : "r"(__float_as_uint(lo)), "r"(__float_as_uint(hi)))
__device__ __forceinline__ void unpack2(ull v, float& lo, float& hi) {
    unsigned l, h;
    asm("mov.b64 {%0, %1}, %2;" : "=r"(l), "=r"(h) : "l"(v));
    lo = __uint_as_float(l); hi = __uint_as_float(h);
}

// ---- tf32 helpers ----
__device__ __forceinline__ unsigned tf32_hi(float v) {
    unsigned h;
    asm("cvt.rna.tf32.f32 %0, %1;" : "=r"(h) : "f"(v));
    return h;
}

#define MMA_TF32(c, a0, a1, a2, a3, b0, b1) \
    asm("mma.sync.aligned.m16n8k8.row.col.f32.tf32.tf32.f32 " \
        "{%0,%1,%2,%3}, {%4,%5,%6,%7}, {%8,%9}, {%0,%1,%2,%3};" \
        : "+f"((c)[0]), "+f"((c)[1]), "+f"((c)[2]), "+f"((c)[3]) \
        : "r"(a0), "r"(a1), "r"(a2), "r"(a3), "r"(b0), "r"(b1))

// ---- scalar compensated MAC (Dekker 2Prod + Fast2Sum with biased accumulator) ----
#define MAC(H, L, a, b) {                         \
    float p  = __fmul_rn((a), (b));               \
    float pe = __fmaf_rn((a), (b), -p);           \
    float t  = __fadd_rn((H), p);                 \
    float z  = __fsub_rn(t, (H));                 \
    float e  = __fsub_rn(p, z);                   \
    (H) = t;                                      \
    (L) = __fadd_rn((L), __fadd_rn(e, pe));       \
}

// ---------------- scratch (static device memory; no runtime allocation) -------------
__device__ float  g_hhi[NB*CI*HH*WW];        // plain-precision conv output (82 MB)
__device__ float  g_w1tf[CI*9*CI];           // w1 transposed to [ic*9+k][oc]
__device__ unsigned g_k32i[NB*PP], g_k32o[NB*PP], g_vi[NB*PP], g_vo[NB*PP];
__device__ int g_segoff[9]  = {0,90000,180000,270000,360000,450000,540000,630000,720000};
__device__ int g_segoff2[9] = {0,CAND,2*CAND,3*CAND,4*CAND,5*CAND,6*CAND,7*CAND,8*CAND};
__device__ unsigned g_cand[NB*CAND];         // candidate anchor ids per image
__device__ int g_pixflag[NB*10000];
__device__ int g_cnt[NB];
__device__ int g_slotofpix[NB*10000];
__device__ int g_pixofslot[NB*CAND];
__device__ float g_hchi[NB*CAND*CI];         // precise h (hi) per candidate pixel slot
__device__ float g_hclo[NB*CAND*CI];         // precise h (lo)
__device__ double g_cboxd[NB*CAND*4];        // exact f64 boxes per candidate
__device__ ull g_ck[NB*CAND], g_cko[NB*CAND];
__device__ unsigned g_cv[NB*CAND], g_cvo[NB*CAND];
__device__ double g_bsort[NB*PRE*4];
__device__ double g_area[NB*PRE];
__device__ float4 g_bsf[NB*PRE];
__device__ float  g_areaf[NB*PRE];
__device__ int   g_valid[NB*PRE];
__device__ unsigned g_mask[NB*PRE*NW];
__device__ unsigned char g_cubtmp[48u<<20];

// ---------------- anchor base (double math, rounded to f32 = np.float32 array) ------
__device__ __forceinline__ void anchor_ab(int k, float& a0, float& a1, float& a2, float& a3) {
    int ri = k / 3, si = k % 3;
    double r = (ri == 0) ? 0.5 : ((ri == 1) ? 1.0 : 2.0);
    double s = (si == 0) ? 8.0 : ((si == 1) ? 16.0 : 32.0);
    double h = 16.0 * s * sqrt(r);
    double w = 16.0 * s * sqrt(1.0 / r);
    a0 = (float)(8.0 - h / 2.0);
    a1 = (float)(8.0 - w / 2.0);
    a2 = (float)(8.0 + h / 2.0);
    a3 = (float)(8.0 + w / 2.0);
}

// ---------------- weight transpose: [oc][ic][k] -> [ic*9+k][oc] ----------------------
__global__ void wtrans(const float* __restrict__ w1) {
    int idx = blockIdx.x * 256 + threadIdx.x;
    if (idx >= CI * 9 * CI) return;
    int oc = idx % CI;
    int t  = idx / CI;
    int kk = t % 9;
    int ic = t / 9;
    g_w1tf[idx] = w1[(oc * CI + ic) * 9 + kk];
}

// -------- tf32 tensor-core conv 3x3 (split hi/lo, 3 cross-products) ------------------
// block: 128 threads (4 warps); tile: 64 pixels x 128 oc; K = 9 kpos x 256 ic.
// warp w computes pixels [w*16, w*16+16) x all 128 oc (16 n-tiles of m16n8k8).
// (R12-proven version)
__global__ __launch_bounds__(128) void conv3t(const float* __restrict__ x,
                                              const float* __restrict__ b1) {
    __shared__ float Ah[64][17], Al[64][17];    // A tile hi/lo  (k16 chunk)
    __shared__ float Bh[16][136], Bl[16][136];  // B tile hi/lo (128 oc + pad)
    int n    = blockIdx.z;
    int ocb  = blockIdx.y * 128;
    int pix0 = blockIdx.x * 64;
    int tid  = threadIdx.x;
    int lane = tid & 31, wid = tid >> 5;
    int gr   = lane >> 2, tg = lane & 3;        // groupID, thread-in-group
    int mrow = wid * 16;

    float c[16][4];
    #pragma unroll
    for (int nt = 0; nt < 16; nt++)
        #pragma unroll
        for (int j = 0; j < 4; j++) c[nt][j] = 0.f;

    int am   = tid & 63;
    int apy  = (pix0 + am) / 100, apx = (pix0 + am) - apy * 100;
    bool apix_ok = (pix0 + am) < 10000;

    for (int kpos = 0; kpos < 9; kpos++) {
        int dy = kpos / 3 - 1, dx = kpos % 3 - 1;
        int gy = apy + dy, gx = apx + dx;
        bool aok = apix_ok && (unsigned)gy < 100u && (unsigned)gx < 100u;
        const float* xbase = x + ((size_t)n * CI * HH + (size_t)gy) * WW + gx;
        for (int icc = 0; icc < 16; icc++) {
            int ic0 = icc * 16;
            // gather A: 64 pixels x 16 ic (shifted x), split hi/lo
            #pragma unroll
            for (int i = 0; i < 8; i++) {
                int kc = i * 2 + (tid >> 6);
                float v = aok ? xbase[(size_t)(ic0 + kc) * (HH * WW)] : 0.f;
                float hv = __uint_as_float(tf32_hi(v));
                Ah[am][kc] = hv;
                Al[am][kc] = __fsub_rn(v, hv);
            }
            // gather B: 16 ic x 128 oc, split hi/lo (float4 loads)
            #pragma unroll
            for (int i = 0; i < 4; i++) {
                int t4 = tid + i * 128;
                int kc = t4 >> 5, o4 = (t4 & 31) * 4;
                float4 v = *(const float4*)&g_w1tf[((ic0 + kc) * 9 + kpos) * CI + ocb + o4];
                float h0 = __uint_as_float(tf32_hi(v.x));
                float h1 = __uint_as_float(tf32_hi(v.y));
                float h2 = __uint_as_float(tf32_hi(v.z));
                float h3 = __uint_as_float(tf32_hi(v.w));
                Bh[kc][o4 + 0] = h0; Bl[kc][o4 + 0] = __fsub_rn(v.x, h0);
                Bh[kc][o4 + 1] = h1; Bl[kc][o4 + 1] = __fsub_rn(v.y, h1);
                Bh[kc][o4 + 2] = h2; Bl[kc][o4 + 2] = __fsub_rn(v.z, h2);
                Bh[kc][o4 + 3] = h3; Bl[kc][o4 + 3] = __fsub_rn(v.w, h3);
            }
            __syncthreads();

            #pragma unroll
            for (int ks = 0; ks < 2; ks++) {
                int k0 = ks * 8;
                unsigned ah0 = __float_as_uint(Ah[mrow + gr][k0 + tg]);
                unsigned ah1 = __float_as_uint(Ah[mrow + gr + 8][k0 + tg]);
                unsigned ah2 = __float_as_uint(Ah[mrow + gr][k0 + tg + 4]);
                unsigned ah3 = __float_as_uint(Ah[mrow + gr + 8][k0 + tg + 4]);
                unsigned al0 = __float_as_uint(Al[mrow + gr][k0 + tg]);
                unsigned al1 = __float_as_uint(Al[mrow + gr + 8][k0 + tg]);
                unsigned al2 = __float_as_uint(Al[mrow + gr][k0 + tg + 4]);
                unsigned al3 = __float_as_uint(Al[mrow + gr + 8][k0 + tg + 4]);
                #pragma unroll
                for (int nt = 0; nt < 16; nt++) {
                    unsigned bh0 = __float_as_uint(Bh[k0 + tg][nt * 8 + gr]);
                    unsigned bh1 = __float_as_uint(Bh[k0 + tg + 4][nt * 8 + gr]);
                    unsigned bl0 = __float_as_uint(Bl[k0 + tg][nt * 8 + gr]);
                    unsigned bl1 = __float_as_uint(Bl[k0 + tg + 4][nt * 8 + gr]);
                    MMA_TF32(c[nt], ah0, ah1, ah2, ah3, bh0, bh1);
                    MMA_TF32(c[nt], ah0, ah1, ah2, ah3, bl0, bl1);
                    MMA_TF32(c[nt], al0, al1, al2, al3, bh0, bh1);
                }
            }
            __syncthreads();
        }
    }

    // epilogue: bias + relu, write h
    int p0 = pix0 + mrow + gr;
    int p1 = p0 + 8;
    #pragma unroll
    for (int nt = 0; nt < 16; nt++) {
        int oc = ocb + nt * 8 + tg * 2;
        float bia = b1[oc], bib = b1[oc + 1];
        if (p0 < 10000) {
            g_hhi[(size_t)(n * CI + oc) * 10000 + p0]       = fmaxf(c[nt][0] + bia, 0.f);
            g_hhi[(size_t)(n * CI + oc + 1) * 10000 + p0]   = fmaxf(c[nt][1] + bib, 0.f);
        }
        if (p1 < 10000) {
            g_hhi[(size_t)(n * CI + oc) * 10000 + p1]       = fmaxf(c[nt][2] + bia, 0.f);
            g_hhi[(size_t)(n * CI + oc + 1) * 10000 + p1]   = fmaxf(c[nt][3] + bib, 0.f);
        }
    }
}

// ------- plain-fp32 fused heads: cls/reg outputs + approx score sort keys ------------
__global__ __launch_bounds__(128) void heads_fast(const float* __restrict__ wc,
                                                  const float* __restrict__ bc,
                                                  const float* __restrict__ wr,
                                                  const float* __restrict__ br,
                                                  float* __restrict__ out) {
    __shared__ float sw1[64][54];
    int n = blockIdx.y;
    int p = blockIdx.x * 128 + threadIdx.x;

    ull H[27];
    #pragma unroll
    for (int o = 0; o < 27; o++) H[o] = 0ull;

    for (int icb = 0; icb < CI; icb += 64) {
        for (int idx = threadIdx.x; idx < 64 * 54; idx += 128) {
            int ic = idx / 54, oc = idx % 54;
            sw1[ic][oc] = (oc < 18) ? wc[oc * CI + icb + ic]
                                    : wr[(oc - 18) * CI + icb + ic];
        }
        __syncthreads();
        if (p < HH * WW) {
            #pragma unroll 1
            for (int ic = 0; ic < 64; ic++) {
                float hh = g_hhi[(size_t)(n * CI + icb + ic) * (HH * WW) + p];
                ull hhp; PACK2(hhp, hh, hh);
                #pragma unroll
                for (int q = 0; q < 27; q++) {
                    ull wp = *(const ull*)&sw1[ic][q * 2];
                    FMA2(H[q], hhp, wp, H[q]);
                }
            }
        }
        __syncthreads();
    }
    if (p >= HH * WW) return;

    float hs[54];
    #pragma unroll
    for (int q = 0; q < 27; q++) unpack2(H[q], hs[q * 2], hs[q * 2 + 1]);

    float l[18];
    #pragma unroll
    for (int c18 = 0; c18 < 18; c18++) {
        l[c18] = hs[c18] + bc[c18];
        int k = c18 >> 1, cc = c18 & 1;
        out[OFF_CLS + (n * 2 + cc) * PP + p * KA + k] = l[c18];
    }
    #pragma unroll
    for (int k = 0; k < KA; k++) {
        float s = 1.f / (1.f + __expf(l[2 * k] - l[2 * k + 1]));
        int idx = n * PP + p * KA + k;
        g_k32i[idx] = __float_as_uint(s);
        g_vi[idx] = (unsigned)(p * KA + k);
    }
    #pragma unroll
    for (int c36 = 0; c36 < 36; c36++) {
        int k = c36 >> 2, j = c36 & 3;
        out[OFF_REG + n * (PP * 4) + (p * KA + k) * 4 + j] = hs[18 + c36] + br[c36];
    }
}

// ---------------- clear per-run state (graph replays reuse buffers) ------------------
__global__ void clearw() {
    int idx = blockIdx.x * 256 + threadIdx.x;
    if (idx < NB * 10000) g_pixflag[idx] = 0;
    if (idx < NB) g_cnt[idx] = 0;
}

// ---------------- mark candidate anchors + their pixels ------------------------------
__global__ void mark() {
    int idx = blockIdx.x * 256 + threadIdx.x;
    if (idx >= NB * CAND) return;
    int n = idx / CAND, r = idx - n * CAND;
    unsigned i = g_vo[n * PP + r];
    g_cand[idx] = i;
    g_pixflag[n * 10000 + i / KA] = 1;
}

// ---------------- compact flagged pixels into slots ----------------------------------
__global__ void compact() {
    int idx = blockIdx.x * 256 + threadIdx.x;
    if (idx >= NB * 10000) return;
    if (g_pixflag[idx]) {
        int n = idx / 10000, pix = idx - n * 10000;
        int s = atomicAdd(&g_cnt[n], 1);
        g_slotofpix[idx] = s;
        g_pixofslot[n * CAND + s] = pix;
    }
}

// ------ precise conv recompute for flagged pixels (compensated FFMA2) ---------------
// block: 128 threads (2 oc each), 4 pixel-slots per block (R8 proven config)
__global__ __launch_bounds__(128) void precise_h(const float* __restrict__ x,
                                                 const float* __restrict__ b1) {
    __shared__ float sxp[4][2304];
    int n = blockIdx.y;
    int s0 = blockIdx.x * 4;
    int cnt = g_cnt[n];
    if (s0 >= cnt) return;
    int tid = threadIdx.x;

    #pragma unroll
    for (int q = 0; q < 4; q++) {
        int sl = s0 + q;
        int pix = g_pixofslot[n * CAND + ((sl < cnt) ? sl : s0)];
        int py = pix / WW, px = pix - py * WW;
        for (int t = tid; t < 2304; t += 128) {
            int ic = t / 9, k = t - ic * 9;
            int ky = k / 3, kx = k - ky * 3;
            int gy = py + ky - 1, gx = px + kx - 1;
            float v = 0.f;
            if ((unsigned)gy < 100u && (unsigned)gx < 100u)
                v = x[((n * CI + ic) * HH + gy) * WW + gx];
            sxp[q][t] = v;
        }
    }
    __syncthreads();

    const float BIAS = 96.0f;
    ull BIASP, NEG1;
    PACK2(BIASP, BIAS, BIAS);
    PACK2(NEG1, -1.0f, -1.0f);
    ull H[4], L[4];
    #pragma unroll
    for (int q = 0; q < 4; q++) { H[q] = BIASP; L[q] = 0ull; }

    const float* wbase = g_w1tf + tid * 2;
    #pragma unroll 4
    for (int t = 0; t < 2304; t++) {
        ull wp = *(const ull*)(wbase + (size_t)t * CI);
        #pragma unroll
        for (int q = 0; q < 4; q++) {
            float xv = sxp[q][t];
            ull xx; PACK2(xx, xv, xv);
            ull Hn, nd, rr;
            FMA2(Hn, xx, wp, H[q]);
            FMA2(nd, Hn, NEG1, H[q]);
            FMA2(rr, xx, wp, nd);
            ADD2(L[q], L[q], rr);
            H[q] = Hn;
        }
    }

    int oc = tid * 2;
    #pragma unroll
    for (int q = 0; q < 4; q++) {
        if (s0 + q < cnt) {
            float h0, h1, l0, l1;
            unpack2(H[q], h0, h1);
            unpack2(L[q], l0, l1);
            size_t base = (size_t)(n * CAND + s0 + q) * CI;
            double v0 = fmax((double)__fsub_rn(h0, BIAS) + (double)l0 + (double)b1[oc], 0.0);
            float vh0 = (float)v0;
            g_hchi[base + oc] = vh0;
            g_hclo[base + oc] = (float)(v0 - (double)vh0);
            double v1 = fmax((double)__fsub_rn(h1, BIAS) + (double)l1 + (double)b1[oc + 1], 0.0);
            float vh1 = (float)v1;
            g_hchi[base + oc + 1] = vh1;
            g_hclo[base + oc + 1] = (float)(v1 - (double)vh1);
        }
    }
}

// ------ exact logits/score/reg + f64 decode for candidates ---------------------------
__global__ void precise_sr(const float* __restrict__ wc,
                           const float* __restrict__ bc,
                           const float* __restrict__ wr,
                           const float* __restrict__ br,
                           const int* __restrict__ pimw,
                           const int* __restrict__ pimh) {
    int idx = blockIdx.x * 256 + threadIdx.x;
    if (idx >= NB * CAND) return;
    int n = idx / CAND, r = idx - n * CAND;
    unsigned i = g_cand[idx];
    int pix = i / KA, k = i - pix * KA;
    int slot = g_slotofpix[n * 10000 + pix];
    size_t base = (size_t)(n * CAND + slot) * CI;

    const float BIAS = 16.0f;
    float Hh[6], Ll[6];
    #pragma unroll
    for (int ch = 0; ch < 6; ch++) { Hh[ch] = BIAS; Ll[ch] = 0.f; }

    for (int ic = 0; ic < CI; ic++) {
        float hh = g_hchi[base + ic];
        float hl = g_hclo[base + ic];
        #pragma unroll
        for (int ch = 0; ch < 6; ch++) {
            float w = (ch < 2) ? wc[(2 * k + ch) * CI + ic]
                               : wr[(4 * k + ch - 2) * CI + ic];
            MAC(Hh[ch], Ll[ch], hh, w);
            Ll[ch] = __fadd_rn(Ll[ch], __fmul_rn(hl, w));
        }
    }

    double l0 = (double)__fsub_rn(Hh[0], BIAS) + (double)Ll[0] + (double)bc[2 * k];
    double l1 = (double)__fsub_rn(Hh[1], BIAS) + (double)Ll[1] + (double)bc[2 * k + 1];
    double score = 1.0 / (1.0 + exp(l0 - l1));
    double dv[4];
    #pragma unroll
    for (int j = 0; j < 4; j++)
        dv[j] = (double)__fsub_rn(Hh[2 + j], BIAS) + (double)Ll[2 + j]
              + (double)br[4 * k + j];

    // f64 decode (anchors replicate numpy f32 arithmetic, then promote)
    int y = pix / WW, x = pix - y * WW;
    float a0, a1, a2, a3;
    anchor_ab(k, a0, a1, a2, a3);
    float sy = (float)(y * 16), sx0 = (float)(x * 16);
    float af0 = sy + a0, af1 = sx0 + a1, af2 = sy + a2, af3 = sx0 + a3;
    float ahf = af2 - af0, awf = af3 - af1;
    float ayf = af0 + 0.5f * ahf, axf = af1 + 0.5f * awf;
    double ah = (double)ahf, aw = (double)awf, ay = (double)ayf, ax = (double)axf;

    double cy = dv[0] * ah + ay, cx = dv[1] * aw + ax;
    double hb = exp(dv[2]) * ah, wb = exp(dv[3]) * aw;

    int wv = pimw[0], hv = pimh[0];
    double imw = (wv > 65536 || wv < 0) ? (double)__int_as_float(wv) : (double)wv;
    double imh = (hv > 65536 || hv < 0) ? (double)__int_as_float(hv) : (double)hv;

    double y1 = fmin(fmax(cy - 0.5 * hb, 0.0), imh);
    double y2 = fmin(fmax(cy + 0.5 * hb, 0.0), imh);
    double x1 = fmin(fmax(cx - 0.5 * wb, 0.0), imw);
    double x2 = fmin(fmax(cx + 0.5 * wb, 0.0), imw);
    bool big = (y2 - y1 >= 16.0) && (x2 - x1 >= 16.0);

    double* bp = &g_cboxd[(size_t)idx * 4];
    bp[0] = y1; bp[1] = x1; bp[2] = y2; bp[3] = x2;
    g_ck[idx] = big ? __double_as_longlong(score) : 0ull;
    g_cv[idx] = (unsigned)r;
}

// ---------------- gather top PRE per batch (from exact candidate sort) ---------------
__global__ void gather_top2() {
    int idx = blockIdx.x * 256 + threadIdx.x;
    if (idx >= NB * PRE) return;
    int n = idx / PRE, rr = idx - n * PRE;
    ull key = g_cko[n * CAND + rr];
    unsigned cs = g_cvo[n * CAND + rr];
    const double* bp = &g_cboxd[((size_t)n * CAND + cs) * 4];
    double y1 = bp[0], x1 = bp[1], y2 = bp[2], x2 = bp[3];
    double* d = &g_bsort[(size_t)idx * 4];
    d[0] = y1; d[1] = x1; d[2] = y2; d[3] = x2;
    double a = (y2 - y1) * (x2 - x1);
    g_area[idx]  = a;
    g_bsf[idx]   = make_float4((float)y1, (float)x1, (float)y2, (float)x2);
    g_areaf[idx] = (float)a;
    g_valid[idx] = (key != 0ull) ? 1 : 0;
}

// ------- NMS mask: f32 IoU with f64 fallback in a guard band around the threshold ----
__global__ __launch_bounds__(96) void nms_mask() {
    int i = blockIdx.x, n = blockIdx.y;
    float4 bi = g_bsf[n * PRE + i];
    float ai = g_areaf[n * PRE + i];
    int lane = threadIdx.x & 31, wp = threadIdx.x >> 5;
    int wstart = i >> 5;
    for (int w = wstart + wp; w < NW; w += 3) {
        int j = w * 32 + lane;
        bool bit = false;
        if (j < PRE && j > i) {
            float4 bj = g_bsf[n * PRE + j];
            float yy1 = fmaxf(bi.x, bj.x);
            float xx1 = fmaxf(bi.y, bj.y);
            float yy2 = fminf(bi.z, bj.z);
            float xx2 = fminf(bi.w, bj.w);
            float inter = fmaxf(yy2 - yy1, 0.f) * fmaxf(xx2 - xx1, 0.f);
            float iou = inter / (ai + g_areaf[n * PRE + j] - inter + 1e-9f);
            if (fabsf(iou - 0.7f) < 1e-4f) {
                const double* di = &g_bsort[((size_t)n * PRE + i) * 4];
                const double* dj = &g_bsort[((size_t)n * PRE + j) * 4];
                double dy1 = fmax(di[0], dj[0]);
                double dx1 = fmax(di[1], dj[1]);
                double dy2 = fmin(di[2], dj[2]);
                double dx2 = fmin(di[3], dj[3]);
                double dint = fmax(dy2 - dy1, 0.0) * fmax(dx2 - dx1, 0.0);
                double diou = dint / (g_area[n * PRE + i] + g_area[n * PRE + j]
                                      - dint + 1e-9);
                bit = diou > 0.7;
            } else {
                bit = iou > 0.7f;
            }
        }
        unsigned m = __ballot_sync(0xffffffffu, bit);
        if (lane == 0) g_mask[((size_t)n * PRE + i) * NW + w] = m;
    }
}

// ------ serial greedy scan, 1 warp per batch; validity prefolded into registers ------
__global__ __launch_bounds__(32) void nms_scan(float* __restrict__ out) {
    int n = blockIdx.x;
    int lane = threadIdx.x;
    unsigned rm0 = 0, rm1 = 0, rm2 = 0;   // lane holds words lane, lane+32, lane+64

    for (int w = 0; w < NW; w++) {
        int j = w * 32 + lane;
        int v = (j < PRE) ? g_valid[n * PRE + j] : 0;
        unsigned word = __ballot_sync(0xffffffffu, v != 0);
        unsigned inv = ~word;
        int slot = w >> 5, src = w & 31;
        if (lane == src) {
            if (slot == 0) rm0 |= inv;
            else if (slot == 1) rm1 |= inv;
            else rm2 |= inv;
        }
    }

    int count = 0;
    for (int i = 0; i < PRE && count < POST; i++) {
        int wi = i >> 5;
        int slot = wi >> 5;
        int src  = wi & 31;
        unsigned myw = (slot == 0) ? rm0 : ((slot == 1) ? rm1 : rm2);
        unsigned word = __shfl_sync(0xffffffffu, myw, src);
        if (!((word >> (i & 31)) & 1u)) {
            if (lane < 4)
                out[OFF_ROIS + (n * POST + count) * 4 + lane] =
                    (float)g_bsort[((size_t)n * PRE + i) * 4 + lane];
            count++;
            const unsigned* mrow = &g_mask[((size_t)n * PRE + i) * NW];
            int w0 = lane;
            int w1 = lane + 32;
            int w2 = lane + 64;
            if (w0 >= wi && w0 < NW) rm0 |= mrow[w0];
            if (w1 >= wi && w1 < NW) rm1 |= mrow[w1];
            if (w2 >= wi && w2 < NW) rm2 |= mrow[w2];
        }
    }
    for (int m = count; m < POST; m++)
        if (lane < 4) out[OFF_ROIS + (n * POST + m) * 4 + lane] = 0.f;
    for (int m = lane; m < POST; m += 32)
        out[OFF_INDS + n * POST + m] = (float)n;
}

// ---------------- anchors output (f32, replicating numpy f32 arithmetic) -------------
__global__ void anchors_k(float* __restrict__ out) {
    int i = blockIdx.x * 256 + threadIdx.x;
    if (i >= PP) return;
    int cell = i / KA, k = i - cell * KA;
    int y = cell / WW, x = cell - y * WW;
    float a0, a1, a2, a3;
    anchor_ab(k, a0, a1, a2, a3);
    float sy = (float)(y * 16), sx = (float)(x * 16);
    out[OFF_ANCH + i * 4 + 0] = sy + a0;
    out[OFF_ANCH + i * 4 + 1] = sx + a1;
    out[OFF_ANCH + i * 4 + 2] = sy + a2;
    out[OFF_ANCH + i * 4 + 3] = sx + a3;
}

// ---------------- launch -------------------------------------------------------------
extern "C" void kernel_launch(void* const* d_in, const int* in_sizes, int n_in,
                              void* d_out, int out_size) {
    const float* x  = (const float*)d_in[0];
    const float* w1 = (const float*)d_in[1];
    const float* b1 = (const float*)d_in[2];
    const float* wc = (const float*)d_in[3];
    const float* bc = (const float*)d_in[4];
    const float* wr = (const float*)d_in[5];
    const float* br = (const float*)d_in[6];
    const int* imw  = (const int*)d_in[7];
    const int* imh  = (const int*)d_in[8];
    float* out = (float*)d_out;

    wtrans<<<(CI * 9 * CI + 255) / 256, 256>>>(w1);
    conv3t<<<dim3(157, 2, NB), 128>>>(x, b1);
    heads_fast<<<dim3(79, NB), 128>>>(wc, bc, wr, br, out);
    clearw<<<(NB * 10000 + 255) / 256, 256>>>();

    void *pt, *poff, *poff2;
    void *pk32i, *pk32o, *pvi, *pvo, *pck, *pcko, *pcv, *pcvo;
    cudaGetSymbolAddress(&pt, g_cubtmp);
    cudaGetSymbolAddress(&poff, g_segoff);
    cudaGetSymbolAddress(&poff2, g_segoff2);
    cudaGetSymbolAddress(&pk32i, g_k32i);
    cudaGetSymbolAddress(&pk32o, g_k32o);
    cudaGetSymbolAddress(&pvi, g_vi);
    cudaGetSymbolAddress(&pvo, g_vo);
    cudaGetSymbolAddress(&pck, g_ck);
    cudaGetSymbolAddress(&pcko, g_cko);
    cudaGetSymbolAddress(&pcv, g_cv);
    cudaGetSymbolAddress(&pcvo, g_cvo);

    // approx preselect sort: low 8 key bits truncated (order within 1.5e-5 score
    // quantum is arbitrary — safe: mark() consumes the top-CAND as a SET and the
    // exact 64-bit sort later restores true ordering)
    size_t tb = sizeof(g_cubtmp);
    cub::DeviceSegmentedRadixSort::SortPairsDescending(
        pt, tb,
        (const unsigned*)pk32i, (unsigned*)pk32o,
        (const unsigned*)pvi, (unsigned*)pvo,
        NB * PP, NB,
        (const int*)poff, (const int*)poff + 1,
        8, 32, (cudaStream_t)0);

    mark<<<(NB * CAND + 255) / 256, 256>>>();
    compact<<<(NB * 10000 + 255) / 256, 256>>>();
    precise_h<<<dim3(CAND / 4, NB), 128>>>(x, b1);
    precise_sr<<<(NB * CAND + 255) / 256, 256>>>(wc, bc, wr, br, imw, imh);

    size_t tb2 = sizeof(g_cubtmp);
    cub::DeviceSegmentedRadixSort::SortPairsDescending(
        pt, tb2,
        (const ull*)pck, (ull*)pcko,
        (const unsigned*)pcv, (unsigned*)pcvo,
        NB * CAND, NB,
        (const int*)poff2, (const int*)poff2 + 1,
        0, 64, (cudaStream_t)0);

    gather_top2<<<(NB * PRE + 255) / 256, 256>>>();
    nms_mask<<<dim3(PRE, NB), 96>>>();
    nms_scan<<<NB, 32>>>(out);
    anchors_k<<<(PP + 255) / 256, 256>>>(out);
}

// round 15
// speedup vs baseline: 1.7052x; 1.2084x over previous
#include <cuda_runtime.h>
#include <cub/cub.cuh>
#include <math.h>

#define NB 8
#define CI 256
#define HH 100
#define WW 100
#define KA 9
#define PP 90000          // anchors per image
#define PRE 3000
#define POST 300
#define NW 94             // 32-bit words to cover PRE bits
#define CAND 3136         // preselected candidates per image (PRE + 136 margin)

#define OFF_CLS  0
#define OFF_REG  1440000
#define OFF_ROIS 4320000
#define OFF_INDS 4329600
#define OFF_ANCH 4332000

typedef unsigned long long ull;

// ---- packed f32x2 ops (sm_103a FFMA2/FADD2, PTX-only) ----
#define FMA2(d, a, b, c) asm("fma.rn.f32x2 %0, %1, %2, %3;" : "=l"(d) : "l"(a), "l"(b), "l"(c))
#define ADD2(d, a, b)    asm("add.rn.f32x2 %0, %1, %2;"     : "=l"(d) : "l"(a), "l"(b))
#define PACK2(d, lo, hi) asm("mov.b64 %0, {%1, %2};"        : "=l"(d) : "r"(__float_as_uint(lo)), "r"(__float_as_uint(hi)))
__device__ __forceinline__ void unpack2(ull v, float& lo, float& hi) {
    unsigned l, h;
    asm("mov.b64 {%0, %1}, %2;" : "=r"(l), "=r"(h) : "l"(v));
    lo = __uint_as_float(l); hi = __uint_as_float(h);
}

// ---- tf32 helpers ----
__device__ __forceinline__ unsigned tf32_hi(float v) {
    unsigned h;
    asm("cvt.rna.tf32.f32 %0, %1;" : "=r"(h) : "f"(v));
    return h;
}

#define MMA_TF32(c, a0, a1, a2, a3, b0, b1) \
    asm("mma.sync.aligned.m16n8k8.row.col.f32.tf32.tf32.f32 " \
        "{%0,%1,%2,%3}, {%4,%5,%6,%7}, {%8,%9}, {%0,%1,%2,%3};" \
        : "+f"((c)[0]), "+f"((c)[1]), "+f"((c)[2]), "+f"((c)[3]) \
        : "r"(a0), "r"(a1), "r"(a2), "r"(a3), "r"(b0), "r"(b1))

// ---- scalar compensated MAC (Dekker 2Prod + Fast2Sum with biased accumulator) ----
#define MAC(H, L, a, b) {                         \
    float p  = __fmul_rn((a), (b));               \
    float pe = __fmaf_rn((a), (b), -p);           \
    float t  = __fadd_rn((H), p);                 \
    float z  = __fsub_rn(t, (H));                 \
    float e  = __fsub_rn(p, z);                   \
    (H) = t;                                      \
    (L) = __fadd_rn((L), __fadd_rn(e, pe));       \
}

// ---------------- scratch (static device memory; no runtime allocation) -------------
__device__ float  g_hhi[NB*CI*HH*WW];        // approx conv output (82 MB)
__device__ float  g_w1tf[CI*9*CI];           // w1 transposed to [ic*9+k][oc]
__device__ unsigned g_k32i[NB*PP], g_k32o[NB*PP], g_vi[NB*PP], g_vo[NB*PP];
__device__ int g_segoff[9]  = {0,90000,180000,270000,360000,450000,540000,630000,720000};
__device__ int g_segoff2[9] = {0,CAND,2*CAND,3*CAND,4*CAND,5*CAND,6*CAND,7*CAND,8*CAND};
__device__ unsigned g_cand[NB*CAND];         // candidate anchor ids per image
__device__ int g_pixflag[NB*10000];
__device__ int g_cnt[NB];
__device__ int g_slotofpix[NB*10000];
__device__ int g_pixofslot[NB*CAND];
__device__ float g_hchi[NB*CAND*CI];         // precise h (hi) per candidate pixel slot
__device__ float g_hclo[NB*CAND*CI];         // precise h (lo)
__device__ double g_cboxd[NB*CAND*4];        // exact f64 boxes per candidate
__device__ ull g_ck[NB*CAND], g_cko[NB*CAND];
__device__ unsigned g_cv[NB*CAND], g_cvo[NB*CAND];
__device__ double g_bsort[NB*PRE*4];
__device__ double g_area[NB*PRE];
__device__ float4 g_bsf[NB*PRE];
__device__ float  g_areaf[NB*PRE];
__device__ int   g_valid[NB*PRE];
__device__ unsigned g_mask[NB*PRE*NW];
__device__ unsigned char g_cubtmp[48u<<20];

// ---------------- anchor base (double math, rounded to f32 = np.float32 array) ------
__device__ __forceinline__ void anchor_ab(int k, float& a0, float& a1, float& a2, float& a3) {
    int ri = k / 3, si = k % 3;
    double r = (ri == 0) ? 0.5 : ((ri == 1) ? 1.0 : 2.0);
    double s = (si == 0) ? 8.0 : ((si == 1) ? 16.0 : 32.0);
    double h = 16.0 * s * sqrt(r);
    double w = 16.0 * s * sqrt(1.0 / r);
    a0 = (float)(8.0 - h / 2.0);
    a1 = (float)(8.0 - w / 2.0);
    a2 = (float)(8.0 + h / 2.0);
    a3 = (float)(8.0 + w / 2.0);
}

// ---------------- weight transpose: [oc][ic][k] -> [ic*9+k][oc] ----------------------
__global__ void wtrans(const float* __restrict__ w1) {
    int idx = blockIdx.x * 256 + threadIdx.x;
    if (idx >= CI * 9 * CI) return;
    int oc = idx % CI;
    int t  = idx / CI;
    int kk = t % 9;
    int ic = t / 9;
    g_w1tf[idx] = w1[(oc * CI + ic) * 9 + kk];
}

// -------- pure-tf32 tensor-core conv 3x3 (single MMA, no hi/lo split) ----------------
// block: 128 threads (4 warps); tile: 64 pixels x 128 oc; K = 9 kpos x 256 ic.
// warp w computes pixels [w*16, w*16+16) x all 128 oc (16 n-tiles of m16n8k8).
// Accuracy: tf32 mantissa (10b) -> h error ~2.4e-4 norm-relative. Only feeds the
// 1e-3-threshold cls/reg outputs and the approx preselect (margin 136 ranks ~1.4e-3
// in score vs ~5e-6 error). Exact selection comes from the precise_* chain.
__global__ __launch_bounds__(128) void conv3t(const float* __restrict__ x,
                                              const float* __restrict__ b1) {
    __shared__ float Ah[64][17];                // A tile tf32  (k16 chunk)
    __shared__ float Bh[16][136];               // B tile tf32 (128 oc + pad)
    int n    = blockIdx.z;
    int ocb  = blockIdx.y * 128;
    int pix0 = blockIdx.x * 64;
    int tid  = threadIdx.x;
    int lane = tid & 31, wid = tid >> 5;
    int gr   = lane >> 2, tg = lane & 3;        // groupID, thread-in-group
    int mrow = wid * 16;

    float c[16][4];
    #pragma unroll
    for (int nt = 0; nt < 16; nt++)
        #pragma unroll
        for (int j = 0; j < 4; j++) c[nt][j] = 0.f;

    int am   = tid & 63;
    int apy  = (pix0 + am) / 100, apx = (pix0 + am) - apy * 100;
    bool apix_ok = (pix0 + am) < 10000;

    for (int kpos = 0; kpos < 9; kpos++) {
        int dy = kpos / 3 - 1, dx = kpos % 3 - 1;
        int gy = apy + dy, gx = apx + dx;
        bool aok = apix_ok && (unsigned)gy < 100u && (unsigned)gx < 100u;
        const float* xbase = x + ((size_t)n * CI * HH + (size_t)gy) * WW + gx;
        for (int icc = 0; icc < 16; icc++) {
            int ic0 = icc * 16;
            // gather A: 64 pixels x 16 ic (shifted x), tf32-rounded
            #pragma unroll
            for (int i = 0; i < 8; i++) {
                int kc = i * 2 + (tid >> 6);
                float v = aok ? xbase[(size_t)(ic0 + kc) * (HH * WW)] : 0.f;
                Ah[am][kc] = __uint_as_float(tf32_hi(v));
            }
            // gather B: 16 ic x 128 oc, tf32-rounded (float4 loads)
            #pragma unroll
            for (int i = 0; i < 4; i++) {
                int t4 = tid + i * 128;
                int kc = t4 >> 5, o4 = (t4 & 31) * 4;
                float4 v = *(const float4*)&g_w1tf[((ic0 + kc) * 9 + kpos) * CI + ocb + o4];
                Bh[kc][o4 + 0] = __uint_as_float(tf32_hi(v.x));
                Bh[kc][o4 + 1] = __uint_as_float(tf32_hi(v.y));
                Bh[kc][o4 + 2] = __uint_as_float(tf32_hi(v.z));
                Bh[kc][o4 + 3] = __uint_as_float(tf32_hi(v.w));
            }
            __syncthreads();

            #pragma unroll
            for (int ks = 0; ks < 2; ks++) {
                int k0 = ks * 8;
                unsigned ah0 = __float_as_uint(Ah[mrow + gr][k0 + tg]);
                unsigned ah1 = __float_as_uint(Ah[mrow + gr + 8][k0 + tg]);
                unsigned ah2 = __float_as_uint(Ah[mrow + gr][k0 + tg + 4]);
                unsigned ah3 = __float_as_uint(Ah[mrow + gr + 8][k0 + tg + 4]);
                #pragma unroll
                for (int nt = 0; nt < 16; nt++) {
                    unsigned bh0 = __float_as_uint(Bh[k0 + tg][nt * 8 + gr]);
                    unsigned bh1 = __float_as_uint(Bh[k0 + tg + 4][nt * 8 + gr]);
                    MMA_TF32(c[nt], ah0, ah1, ah2, ah3, bh0, bh1);
                }
            }
            __syncthreads();
        }
    }

    // epilogue: bias + relu, write h
    int p0 = pix0 + mrow + gr;
    int p1 = p0 + 8;
    #pragma unroll
    for (int nt = 0; nt < 16; nt++) {
        int oc = ocb + nt * 8 + tg * 2;
        float bia = b1[oc], bib = b1[oc + 1];
        if (p0 < 10000) {
            g_hhi[(size_t)(n * CI + oc) * 10000 + p0]       = fmaxf(c[nt][0] + bia, 0.f);
            g_hhi[(size_t)(n * CI + oc + 1) * 10000 + p0]   = fmaxf(c[nt][1] + bib, 0.f);
        }
        if (p1 < 10000) {
            g_hhi[(size_t)(n * CI + oc) * 10000 + p1]       = fmaxf(c[nt][2] + bia, 0.f);
            g_hhi[(size_t)(n * CI + oc + 1) * 10000 + p1]   = fmaxf(c[nt][3] + bib, 0.f);
        }
    }
}

// ------- plain-fp32 fused heads: cls/reg outputs + approx score sort keys ------------
__global__ __launch_bounds__(128) void heads_fast(const float* __restrict__ wc,
                                                  const float* __restrict__ bc,
                                                  const float* __restrict__ wr,
                                                  const float* __restrict__ br,
                                                  float* __restrict__ out) {
    __shared__ float sw1[64][54];
    int n = blockIdx.y;
    int p = blockIdx.x * 128 + threadIdx.x;

    ull H[27];
    #pragma unroll
    for (int o = 0; o < 27; o++) H[o] = 0ull;

    for (int icb = 0; icb < CI; icb += 64) {
        for (int idx = threadIdx.x; idx < 64 * 54; idx += 128) {
            int ic = idx / 54, oc = idx % 54;
            sw1[ic][oc] = (oc < 18) ? wc[oc * CI + icb + ic]
                                    : wr[(oc - 18) * CI + icb + ic];
        }
        __syncthreads();
        if (p < HH * WW) {
            #pragma unroll 1
            for (int ic = 0; ic < 64; ic++) {
                float hh = g_hhi[(size_t)(n * CI + icb + ic) * (HH * WW) + p];
                ull hhp; PACK2(hhp, hh, hh);
                #pragma unroll
                for (int q = 0; q < 27; q++) {
                    ull wp = *(const ull*)&sw1[ic][q * 2];
                    FMA2(H[q], hhp, wp, H[q]);
                }
            }
        }
        __syncthreads();
    }
    if (p >= HH * WW) return;

    float hs[54];
    #pragma unroll
    for (int q = 0; q < 27; q++) unpack2(H[q], hs[q * 2], hs[q * 2 + 1]);

    float l[18];
    #pragma unroll
    for (int c18 = 0; c18 < 18; c18++) {
        l[c18] = hs[c18] + bc[c18];
        int k = c18 >> 1, cc = c18 & 1;
        out[OFF_CLS + (n * 2 + cc) * PP + p * KA + k] = l[c18];
    }
    #pragma unroll
    for (int k = 0; k < KA; k++) {
        float s = 1.f / (1.f + __expf(l[2 * k] - l[2 * k + 1]));
        int idx = n * PP + p * KA + k;
        g_k32i[idx] = __float_as_uint(s);
        g_vi[idx] = (unsigned)(p * KA + k);
    }
    #pragma unroll
    for (int c36 = 0; c36 < 36; c36++) {
        int k = c36 >> 2, j = c36 & 3;
        out[OFF_REG + n * (PP * 4) + (p * KA + k) * 4 + j] = hs[18 + c36] + br[c36];
    }
}

// ---------------- clear per-run state (graph replays reuse buffers) ------------------
__global__ void clearw() {
    int idx = blockIdx.x * 256 + threadIdx.x;
    if (idx < NB * 10000) g_pixflag[idx] = 0;
    if (idx < NB) g_cnt[idx] = 0;
}

// ---------------- mark candidate anchors + their pixels ------------------------------
__global__ void mark() {
    int idx = blockIdx.x * 256 + threadIdx.x;
    if (idx >= NB * CAND) return;
    int n = idx / CAND, r = idx - n * CAND;
    unsigned i = g_vo[n * PP + r];
    g_cand[idx] = i;
    g_pixflag[n * 10000 + i / KA] = 1;
}

// ---------------- compact flagged pixels into slots ----------------------------------
__global__ void compact() {
    int idx = blockIdx.x * 256 + threadIdx.x;
    if (idx >= NB * 10000) return;
    if (g_pixflag[idx]) {
        int n = idx / 10000, pix = idx - n * 10000;
        int s = atomicAdd(&g_cnt[n], 1);
        g_slotofpix[idx] = s;
        g_pixofslot[n * CAND + s] = pix;
    }
}

// ------ precise conv recompute for flagged pixels (compensated FFMA2) ---------------
// block: 128 threads (2 oc each), 4 pixel-slots per block; k unrolled x2 (float2 x)
__global__ __launch_bounds__(128) void precise_h(const float* __restrict__ x,
                                                 const float* __restrict__ b1) {
    __shared__ float sxp[4][2304];
    int n = blockIdx.y;
    int s0 = blockIdx.x * 4;
    int cnt = g_cnt[n];
    if (s0 >= cnt) return;
    int tid = threadIdx.x;

    #pragma unroll
    for (int q = 0; q < 4; q++) {
        int sl = s0 + q;
        int pix = g_pixofslot[n * CAND + ((sl < cnt) ? sl : s0)];
        int py = pix / WW, px = pix - py * WW;
        for (int t = tid; t < 2304; t += 128) {
            int ic = t / 9, k = t - ic * 9;
            int ky = k / 3, kx = k - ky * 3;
            int gy = py + ky - 1, gx = px + kx - 1;
            float v = 0.f;
            if ((unsigned)gy < 100u && (unsigned)gx < 100u)
                v = x[((n * CI + ic) * HH + gy) * WW + gx];
            sxp[q][t] = v;
        }
    }
    __syncthreads();

    const float BIAS = 96.0f;
    ull BIASP, NEG1;
    PACK2(BIASP, BIAS, BIAS);
    PACK2(NEG1, -1.0f, -1.0f);
    ull H[4], L[4];
    #pragma unroll
    for (int q = 0; q < 4; q++) { H[q] = BIASP; L[q] = 0ull; }

    const float* wbase = g_w1tf + tid * 2;
    #pragma unroll 2
    for (int t = 0; t < 2304; t += 2) {
        ull wp0 = *(const ull*)(wbase + (size_t)t * CI);
        ull wp1 = *(const ull*)(wbase + (size_t)(t + 1) * CI);
        #pragma unroll
        for (int q = 0; q < 4; q++) {
            float2 xv = *(const float2*)&sxp[q][t];
            ull xx, Hn, nd, rr;
            PACK2(xx, xv.x, xv.x);
            FMA2(Hn, xx, wp0, H[q]);
            FMA2(nd, Hn, NEG1, H[q]);
            FMA2(rr, xx, wp0, nd);
            ADD2(L[q], L[q], rr);
            H[q] = Hn;
            PACK2(xx, xv.y, xv.y);
            FMA2(Hn, xx, wp1, H[q]);
            FMA2(nd, Hn, NEG1, H[q]);
            FMA2(rr, xx, wp1, nd);
            ADD2(L[q], L[q], rr);
            H[q] = Hn;
        }
    }

    int oc = tid * 2;
    #pragma unroll
    for (int q = 0; q < 4; q++) {
        if (s0 + q < cnt) {
            float h0, h1, l0, l1;
            unpack2(H[q], h0, h1);
            unpack2(L[q], l0, l1);
            size_t base = (size_t)(n * CAND + s0 + q) * CI;
            double v0 = fmax((double)__fsub_rn(h0, BIAS) + (double)l0 + (double)b1[oc], 0.0);
            float vh0 = (float)v0;
            g_hchi[base + oc] = vh0;
            g_hclo[base + oc] = (float)(v0 - (double)vh0);
            double v1 = fmax((double)__fsub_rn(h1, BIAS) + (double)l1 + (double)b1[oc + 1], 0.0);
            float vh1 = (float)v1;
            g_hchi[base + oc + 1] = vh1;
            g_hclo[base + oc + 1] = (float)(v1 - (double)vh1);
        }
    }
}

// ------ exact logits/score/reg + f64 decode for candidates ---------------------------
__global__ void precise_sr(const float* __restrict__ wc,
                           const float* __restrict__ bc,
                           const float* __restrict__ wr,
                           const float* __restrict__ br,
                           const int* __restrict__ pimw,
                           const int* __restrict__ pimh) {
    int idx = blockIdx.x * 256 + threadIdx.x;
    if (idx >= NB * CAND) return;
    int n = idx / CAND, r = idx - n * CAND;
    unsigned i = g_cand[idx];
    int pix = i / KA, k = i - pix * KA;
    int slot = g_slotofpix[n * 10000 + pix];
    size_t base = (size_t)(n * CAND + slot) * CI;

    const float BIAS = 16.0f;
    float Hh[6], Ll[6];
    #pragma unroll
    for (int ch = 0; ch < 6; ch++) { Hh[ch] = BIAS; Ll[ch] = 0.f; }

    for (int ic = 0; ic < CI; ic++) {
        float hh = g_hchi[base + ic];
        float hl = g_hclo[base + ic];
        #pragma unroll
        for (int ch = 0; ch < 6; ch++) {
            float w = (ch < 2) ? wc[(2 * k + ch) * CI + ic]
                               : wr[(4 * k + ch - 2) * CI + ic];
            MAC(Hh[ch], Ll[ch], hh, w);
            Ll[ch] = __fadd_rn(Ll[ch], __fmul_rn(hl, w));
        }
    }

    double l0 = (double)__fsub_rn(Hh[0], BIAS) + (double)Ll[0] + (double)bc[2 * k];
    double l1 = (double)__fsub_rn(Hh[1], BIAS) + (double)Ll[1] + (double)bc[2 * k + 1];
    double score = 1.0 / (1.0 + exp(l0 - l1));
    double dv[4];
    #pragma unroll
    for (int j = 0; j < 4; j++)
        dv[j] = (double)__fsub_rn(Hh[2 + j], BIAS) + (double)Ll[2 + j]
              + (double)br[4 * k + j];

    // f64 decode (anchors replicate numpy f32 arithmetic, then promote)
    int y = pix / WW, x = pix - y * WW;
    float a0, a1, a2, a3;
    anchor_ab(k, a0, a1, a2, a3);
    float sy = (float)(y * 16), sx0 = (float)(x * 16);
    float af0 = sy + a0, af1 = sx0 + a1, af2 = sy + a2, af3 = sx0 + a3;
    float ahf = af2 - af0, awf = af3 - af1;
    float ayf = af0 + 0.5f * ahf, axf = af1 + 0.5f * awf;
    double ah = (double)ahf, aw = (double)awf, ay = (double)ayf, ax = (double)axf;

    double cy = dv[0] * ah + ay, cx = dv[1] * aw + ax;
    double hb = exp(dv[2]) * ah, wb = exp(dv[3]) * aw;

    int wv = pimw[0], hv = pimh[0];
    double imw = (wv > 65536 || wv < 0) ? (double)__int_as_float(wv) : (double)wv;
    double imh = (hv > 65536 || hv < 0) ? (double)__int_as_float(hv) : (double)hv;

    double y1 = fmin(fmax(cy - 0.5 * hb, 0.0), imh);
    double y2 = fmin(fmax(cy + 0.5 * hb, 0.0), imh);
    double x1 = fmin(fmax(cx - 0.5 * wb, 0.0), imw);
    double x2 = fmin(fmax(cx + 0.5 * wb, 0.0), imw);
    bool big = (y2 - y1 >= 16.0) && (x2 - x1 >= 16.0);

    double* bp = &g_cboxd[(size_t)idx * 4];
    bp[0] = y1; bp[1] = x1; bp[2] = y2; bp[3] = x2;
    g_ck[idx] = big ? __double_as_longlong(score) : 0ull;
    g_cv[idx] = (unsigned)r;
}

// ---------------- gather top PRE per batch (from exact candidate sort) ---------------
__global__ void gather_top2() {
    int idx = blockIdx.x * 256 + threadIdx.x;
    if (idx >= NB * PRE) return;
    int n = idx / PRE, rr = idx - n * PRE;
    ull key = g_cko[n * CAND + rr];
    unsigned cs = g_cvo[n * CAND + rr];
    const double* bp = &g_cboxd[((size_t)n * CAND + cs) * 4];
    double y1 = bp[0], x1 = bp[1], y2 = bp[2], x2 = bp[3];
    double* d = &g_bsort[(size_t)idx * 4];
    d[0] = y1; d[1] = x1; d[2] = y2; d[3] = x2;
    double a = (y2 - y1) * (x2 - x1);
    g_area[idx]  = a;
    g_bsf[idx]   = make_float4((float)y1, (float)x1, (float)y2, (float)x2);
    g_areaf[idx] = (float)a;
    g_valid[idx] = (key != 0ull) ? 1 : 0;
}

// ------- NMS mask: f32 IoU with f64 fallback in a guard band around the threshold ----
__global__ __launch_bounds__(96) void nms_mask() {
    int i = blockIdx.x, n = blockIdx.y;
    float4 bi = g_bsf[n * PRE + i];
    float ai = g_areaf[n * PRE + i];
    int lane = threadIdx.x & 31, wp = threadIdx.x >> 5;
    int wstart = i >> 5;
    for (int w = wstart + wp; w < NW; w += 3) {
        int j = w * 32 + lane;
        bool bit = false;
        if (j < PRE && j > i) {
            float4 bj = g_bsf[n * PRE + j];
            float yy1 = fmaxf(bi.x, bj.x);
            float xx1 = fmaxf(bi.y, bj.y);
            float yy2 = fminf(bi.z, bj.z);
            float xx2 = fminf(bi.w, bj.w);
            float inter = fmaxf(yy2 - yy1, 0.f) * fmaxf(xx2 - xx1, 0.f);
            float iou = inter / (ai + g_areaf[n * PRE + j] - inter + 1e-9f);
            if (fabsf(iou - 0.7f) < 1e-4f) {
                const double* di = &g_bsort[((size_t)n * PRE + i) * 4];
                const double* dj = &g_bsort[((size_t)n * PRE + j) * 4];
                double dy1 = fmax(di[0], dj[0]);
                double dx1 = fmax(di[1], dj[1]);
                double dy2 = fmin(di[2], dj[2]);
                double dx2 = fmin(di[3], dj[3]);
                double dint = fmax(dy2 - dy1, 0.0) * fmax(dx2 - dx1, 0.0);
                double diou = dint / (g_area[n * PRE + i] + g_area[n * PRE + j]
                                      - dint + 1e-9);
                bit = diou > 0.7;
            } else {
                bit = iou > 0.7f;
            }
        }
        unsigned m = __ballot_sync(0xffffffffu, bit);
        if (lane == 0) g_mask[((size_t)n * PRE + i) * NW + w] = m;
    }
}

// ------ serial greedy scan, 1 warp per batch; validity prefolded into registers ------
__global__ __launch_bounds__(32) void nms_scan(float* __restrict__ out) {
    int n = blockIdx.x;
    int lane = threadIdx.x;
    unsigned rm0 = 0, rm1 = 0, rm2 = 0;   // lane holds words lane, lane+32, lane+64

    for (int w = 0; w < NW; w++) {
        int j = w * 32 + lane;
        int v = (j < PRE) ? g_valid[n * PRE + j] : 0;
        unsigned word = __ballot_sync(0xffffffffu, v != 0);
        unsigned inv = ~word;
        int slot = w >> 5, src = w & 31;
        if (lane == src) {
            if (slot == 0) rm0 |= inv;
            else if (slot == 1) rm1 |= inv;
            else rm2 |= inv;
        }
    }

    int count = 0;
    for (int i = 0; i < PRE && count < POST; i++) {
        int wi = i >> 5;
        int slot = wi >> 5;
        int src  = wi & 31;
        unsigned myw = (slot == 0) ? rm0 : ((slot == 1) ? rm1 : rm2);
        unsigned word = __shfl_sync(0xffffffffu, myw, src);
        if (!((word >> (i & 31)) & 1u)) {
            if (lane < 4)
                out[OFF_ROIS + (n * POST + count) * 4 + lane] =
                    (float)g_bsort[((size_t)n * PRE + i) * 4 + lane];
            count++;
            const unsigned* mrow = &g_mask[((size_t)n * PRE + i) * NW];
            int w0 = lane;
            int w1 = lane + 32;
            int w2 = lane + 64;
            if (w0 >= wi && w0 < NW) rm0 |= mrow[w0];
            if (w1 >= wi && w1 < NW) rm1 |= mrow[w1];
            if (w2 >= wi && w2 < NW) rm2 |= mrow[w2];
        }
    }
    for (int m = count; m < POST; m++)
        if (lane < 4) out[OFF_ROIS + (n * POST + m) * 4 + lane] = 0.f;
    for (int m = lane; m < POST; m += 32)
        out[OFF_INDS + n * POST + m] = (float)n;
}

// ---------------- anchors output (f32, replicating numpy f32 arithmetic) -------------
__global__ void anchors_k(float* __restrict__ out) {
    int i = blockIdx.x * 256 + threadIdx.x;
    if (i >= PP) return;
    int cell = i / KA, k = i - cell * KA;
    int y = cell / WW, x = cell - y * WW;
    float a0, a1, a2, a3;
    anchor_ab(k, a0, a1, a2, a3);
    float sy = (float)(y * 16), sx = (float)(x * 16);
    out[OFF_ANCH + i * 4 + 0] = sy + a0;
    out[OFF_ANCH + i * 4 + 1] = sx + a1;
    out[OFF_ANCH + i * 4 + 2] = sy + a2;
    out[OFF_ANCH + i * 4 + 3] = sx + a3;
}

// ---------------- launch -------------------------------------------------------------
extern "C" void kernel_launch(void* const* d_in, const int* in_sizes, int n_in,
                              void* d_out, int out_size) {
    const float* x  = (const float*)d_in[0];
    const float* w1 = (const float*)d_in[1];
    const float* b1 = (const float*)d_in[2];
    const float* wc = (const float*)d_in[3];
    const float* bc = (const float*)d_in[4];
    const float* wr = (const float*)d_in[5];
    const float* br = (const float*)d_in[6];
    const int* imw  = (const int*)d_in[7];
    const int* imh  = (const int*)d_in[8];
    float* out = (float*)d_out;

    wtrans<<<(CI * 9 * CI + 255) / 256, 256>>>(w1);
    conv3t<<<dim3(157, 2, NB), 128>>>(x, b1);
    heads_fast<<<dim3(79, NB), 128>>>(wc, bc, wr, br, out);
    clearw<<<(NB * 10000 + 255) / 256, 256>>>();

    void *pt, *poff, *poff2;
    void *pk32i, *pk32o, *pvi, *pvo, *pck, *pcko, *pcv, *pcvo;
    cudaGetSymbolAddress(&pt, g_cubtmp);
    cudaGetSymbolAddress(&poff, g_segoff);
    cudaGetSymbolAddress(&poff2, g_segoff2);
    cudaGetSymbolAddress(&pk32i, g_k32i);
    cudaGetSymbolAddress(&pk32o, g_k32o);
    cudaGetSymbolAddress(&pvi, g_vi);
    cudaGetSymbolAddress(&pvo, g_vo);
    cudaGetSymbolAddress(&pck, g_ck);
    cudaGetSymbolAddress(&pcko, g_cko);
    cudaGetSymbolAddress(&pcv, g_cv);
    cudaGetSymbolAddress(&pcvo, g_cvo);

    // approx preselect sort: low 8 key bits truncated (order within 1.5e-5 score
    // quantum is arbitrary — safe: mark() consumes the top-CAND as a SET and the
    // exact 64-bit sort later restores true ordering)
    size_t tb = sizeof(g_cubtmp);
    cub::DeviceSegmentedRadixSort::SortPairsDescending(
        pt, tb,
        (const unsigned*)pk32i, (unsigned*)pk32o,
        (const unsigned*)pvi, (unsigned*)pvo,
        NB * PP, NB,
        (const int*)poff, (const int*)poff + 1,
        8, 32, (cudaStream_t)0);

    mark<<<(NB * CAND + 255) / 256, 256>>>();
    compact<<<(NB * 10000 + 255) / 256, 256>>>();
    precise_h<<<dim3(CAND / 4, NB), 128>>>(x, b1);
    precise_sr<<<(NB * CAND + 255) / 256, 256>>>(wc, bc, wr, br, imw, imh);

    size_t tb2 = sizeof(g_cubtmp);
    cub::DeviceSegmentedRadixSort::SortPairsDescending(
        pt, tb2,
        (const ull*)pck, (ull*)pcko,
        (const unsigned*)pcv, (unsigned*)pcvo,
        NB * CAND, NB,
        (const int*)poff2, (const int*)poff2 + 1,
        0, 64, (cudaStream_t)0);

    gather_top2<<<(NB * PRE + 255) / 256, 256>>>();
    nms_mask<<<dim3(PRE, NB), 96>>>();
    nms_scan<<<NB, 32>>>(out);
    anchors_k<<<(PP + 255) / 256, 256>>>(out);
}